// round 2
// baseline (speedup 1.0000x reference)
#include <cuda_runtime.h>
#include <stdint.h>

// ---------------- configuration ----------------
#define NUM_BINS   (1 << 20)     // top-20-bit bins of positive float bit patterns
#define NCHUNK     1024
#define CHUNK      1024          // NCHUNK * CHUNK == NUM_BINS
#define CAND_CAP   (1 << 20)     // candidate buffer (oversized for safety)
#define LAST_DIM   16384

// ---------------- device state (persists across launches -> cleared each call) ----
__device__ int                g_hist[NUM_BINS];
__device__ int                g_chunk[NCHUNK];
__device__ unsigned long long g_cand[CAND_CAP];   // (bits << 32) | flat_index
__device__ int                g_cand_n;
__device__ unsigned int       g_bstar;
__device__ int                g_need;

// ---------------- kernels ----------------
__global__ void k_clear() {
    int i = blockIdx.x * blockDim.x + threadIdx.x;
    int stride = gridDim.x * blockDim.x;
    for (int b = i; b < NUM_BINS; b += stride) g_hist[b] = 0;
    if (i == 0) g_cand_n = 0;
}

__device__ __forceinline__ void hist_one(float v) {
    if (v > 0.0f) {
        unsigned bits = __float_as_uint(v);
        atomicAdd(&g_hist[bits >> 12], 1);
    }
}

__global__ void k_hist(const float4* __restrict__ x, int n4) {
    int i = blockIdx.x * blockDim.x + threadIdx.x;
    int stride = gridDim.x * blockDim.x;
    for (; i < n4; i += stride) {
        float4 v = x[i];
        hist_one(v.x);
        hist_one(v.y);
        hist_one(v.z);
        hist_one(v.w);
    }
}

__global__ void k_chunksum() {
    __shared__ int red[256];
    int c = blockIdx.x;          // NCHUNK blocks
    int t = threadIdx.x;         // 256 threads
    int sum = 0;
    for (int j = t; j < CHUNK; j += 256) sum += g_hist[c * CHUNK + j];
    red[t] = sum;
    __syncthreads();
    for (int off = 128; off > 0; off >>= 1) {
        if (t < off) red[t] += red[t + off];
        __syncthreads();
    }
    if (t == 0) g_chunk[c] = red[0];
}

// One block, 1024 threads. Finds cutoff bin b* and the number of elements
// inside b* that survive (need).
__global__ void k_findthr(const int* kptr, int num_samples) {
    __shared__ int s[NCHUNK];
    __shared__ int sh_c, sh_above, sh_nkeep;
    int t = threadIdx.x;

    int kk = (kptr != nullptr) ? kptr[0] : 64;
    int n_keep = kk * num_samples;

    // ---- pass 1: inclusive suffix scan over chunk sums ----
    s[t] = g_chunk[t];
    __syncthreads();
    for (int off = 1; off < NCHUNK; off <<= 1) {
        int v = (t + off < NCHUNK) ? s[t + off] : 0;
        __syncthreads();
        s[t] += v;
        __syncthreads();
    }
    // s[t] = sum of chunks t..end
    if (t == 0) sh_nkeep = (s[0] < n_keep) ? s[0] : n_keep;  // clamp to #positives
    __syncthreads();
    n_keep = sh_nkeep;

    int above = (t + 1 < NCHUNK) ? s[t + 1] : 0;
    if (s[t] >= n_keep && above < n_keep) {
        sh_c = t;
        sh_above = above;
    }
    __syncthreads();
    int cstar = sh_c;
    int above_c = sh_above;

    // ---- pass 2: inclusive suffix scan within the cutoff chunk ----
    s[t] = g_hist[cstar * CHUNK + t];
    __syncthreads();
    for (int off = 1; off < CHUNK; off <<= 1) {
        int v = (t + off < CHUNK) ? s[t + off] : 0;
        __syncthreads();
        s[t] += v;
        __syncthreads();
    }
    int above_b = (t + 1 < CHUNK) ? s[t + 1] : 0;
    int tot_above = above_c + above_b;
    if (s[t] + above_c >= n_keep && tot_above < n_keep) {
        g_bstar = (unsigned)(cstar * CHUNK + t);
        g_need  = n_keep - tot_above;
    }
}

__device__ __forceinline__ float out_one(float v, unsigned idx, unsigned bstar) {
    if (v > 0.0f) {
        unsigned bits = __float_as_uint(v);
        unsigned b = bits >> 12;
        if (b > bstar) return v;
        if (b == bstar) {
            int p = atomicAdd(&g_cand_n, 1);
            if (p < CAND_CAP)
                g_cand[p] = ((unsigned long long)bits << 32) | (unsigned long long)idx;
        }
    }
    return 0.0f;
}

__global__ void k_out(const float4* __restrict__ x, float4* __restrict__ out, int n4) {
    unsigned bstar = g_bstar;
    int i = blockIdx.x * blockDim.x + threadIdx.x;
    int stride = gridDim.x * blockDim.x;
    for (; i < n4; i += stride) {
        float4 v = x[i];
        unsigned base = (unsigned)i * 4u;
        float4 o;
        o.x = out_one(v.x, base + 0u, bstar);
        o.y = out_one(v.y, base + 1u, bstar);
        o.z = out_one(v.z, base + 2u, bstar);
        o.w = out_one(v.w, base + 3u, bstar);
        out[i] = o;
    }
}

// Exact top-k tie-break inside the cutoff bin: larger value first; for equal
// values, smaller flat index first (matches jax.lax.top_k).
__global__ void k_resolve(float* __restrict__ out) {
    int n = g_cand_n;
    if (n > CAND_CAP) n = CAND_CAP;
    int need = g_need;
    int i = blockIdx.x * blockDim.x + threadIdx.x;
    int stride = gridDim.x * blockDim.x;
    for (; i < n; i += stride) {
        unsigned long long ci = g_cand[i];
        unsigned bits_i = (unsigned)(ci >> 32);
        unsigned idx_i  = (unsigned)ci;
        int rank = 0;
        for (int j = 0; j < n; j++) {
            unsigned long long cj = g_cand[j];
            unsigned bits_j = (unsigned)(cj >> 32);
            unsigned idx_j  = (unsigned)cj;
            rank += (bits_j > bits_i) || (bits_j == bits_i && idx_j < idx_i);
        }
        if (rank < need) out[idx_i] = __uint_as_float(bits_i);
    }
}

// ---------------- launch ----------------
extern "C" void kernel_launch(void* const* d_in, const int* in_sizes, int n_in,
                              void* d_out, int out_size) {
    const float* x   = (const float*)d_in[0];
    const int* kptr  = (n_in >= 2) ? (const int*)d_in[1] : nullptr;
    float* out       = (float*)d_out;

    int n  = in_sizes[0];
    int n4 = n / 4;
    int num_samples = n / LAST_DIM;

    k_clear   <<<1024, 256>>>();
    k_hist    <<<2048, 256>>>((const float4*)x, n4);
    k_chunksum<<<NCHUNK, 256>>>();
    k_findthr <<<1, 1024>>>(kptr, num_samples);
    k_out     <<<2048, 256>>>((const float4*)x, (float4*)out, n4);
    k_resolve <<<256, 256>>>(out);
}

// round 3
// speedup vs baseline: 5.3408x; 5.3408x over previous
#include <cuda_runtime.h>
#include <stdint.h>

#define NBIN      4096
#define CAND_CAP  (8*1024*1024)
#define CAP2      16384
#define SBUF_CAP  1024
#define LAST_DIM  16384

// ---------------- persistent device state (cleared every launch) ----------------
__device__ int                g_shist[NBIN];   // sampled histogram (12-bit key)
__device__ int                g_hist1[NBIN];   // candidate histogram level 1
__device__ int                g_hist2[NBIN];   // candidate histogram level 2
__device__ unsigned long long g_cand[CAND_CAP];
__device__ unsigned long long g_cand2[CAP2];
__device__ int g_cand_n, g_cand2_n;
__device__ int g_pivot;                         // coarse bin pivot (12-bit key space)
__device__ int g_c1, g_above1;
__device__ int g_b2, g_need;

// ---------------- init ----------------
__global__ void k_init() {
    int i = blockIdx.x * blockDim.x + threadIdx.x;
    if (i < NBIN) { g_shist[i] = 0; g_hist1[i] = 0; g_hist2[i] = 0; }
    if (i == 0) {
        g_cand_n = 0; g_cand2_n = 0;
        g_pivot = 1;                  // fallback: all positives are candidates
        g_c1 = 0x7fffffff; g_above1 = 0;
        g_b2 = 0x7fffffff; g_need = 0;
    }
}

// ---------------- sampled histogram (1/64 of elements) ----------------
__global__ void k_sample(const float4* __restrict__ x, int nsamp4) {
    __shared__ int h[NBIN];
    for (int j = threadIdx.x; j < NBIN; j += blockDim.x) h[j] = 0;
    __syncthreads();
    int i = blockIdx.x * blockDim.x + threadIdx.x;
    int stride = gridDim.x * blockDim.x;
    for (; i < nsamp4; i += stride) {
        float4 v = x[(size_t)i * 64];
        int b0 = __float_as_int(v.x), b1 = __float_as_int(v.y);
        int b2 = __float_as_int(v.z), b3 = __float_as_int(v.w);
        if (b0 > 0) atomicAdd(&h[b0 >> 19], 1);
        if (b1 > 0) atomicAdd(&h[b1 >> 19], 1);
        if (b2 > 0) atomicAdd(&h[b2 >> 19], 1);
        if (b3 > 0) atomicAdd(&h[b3 >> 19], 1);
    }
    __syncthreads();
    for (int j = threadIdx.x; j < NBIN; j += blockDim.x) {
        int c = h[j];
        if (c) atomicAdd(&g_shist[j], c);
    }
}

// ---------------- suffix-boundary finder (one block, 1024 threads) ----------------
// finds bin b with suffix(b) >= target && suffix(b+1) < target.
// returns b (-1 if none) and suffix(b+1) to every thread.
__device__ void suffix_find(const int* hist, long long target, int& b_out, int& after_out) {
    __shared__ int ssum[1024];
    __shared__ int sh_b, sh_after;
    int t = threadIdx.x;
    if (t == 0) { sh_b = -1; sh_after = 0; }
    int b0 = 4 * t;
    int h0 = hist[b0], h1 = hist[b0 + 1], h2 = hist[b0 + 2], h3 = hist[b0 + 3];
    int l3 = h3, l2 = h2 + l3, l1 = h1 + l2, l0 = h0 + l1;
    ssum[t] = l0;
    __syncthreads();
    for (int off = 1; off < 1024; off <<= 1) {
        int v = (t + off < 1024) ? ssum[t + off] : 0;
        __syncthreads();
        ssum[t] += v;
        __syncthreads();
    }
    int after = (t + 1 < 1024) ? ssum[t + 1] : 0;
    long long s0 = (long long)l0 + after, s1 = (long long)l1 + after;
    long long s2 = (long long)l2 + after, s3 = (long long)l3 + after, s4 = after;
    if (s0 >= target && s1 < target) { sh_b = b0;     sh_after = (int)s1; }
    if (s1 >= target && s2 < target) { sh_b = b0 + 1; sh_after = (int)s2; }
    if (s2 >= target && s3 < target) { sh_b = b0 + 2; sh_after = (int)s3; }
    if (s3 >= target && s4 < target) { sh_b = b0 + 3; sh_after = (int)s4; }
    __syncthreads();
    b_out = sh_b; after_out = sh_after;
}

// ---------------- pick pivot from sampled histogram ----------------
__global__ void k_pivot(const int* kptr, int num_samples) {
    int kk = (kptr != nullptr) ? kptr[0] : 64;
    long long nk = (long long)kk * num_samples;
    long long target = (nk * 135) / (100 * 64) + 256;   // 1.35x expected sample count + slack
    if (target < 1) target = 1;
    int b, after;
    suffix_find(g_shist, target, b, after);
    if (threadIdx.x == 0) {
        if (b >= 2) g_pivot = b - 1;     // one extra bin of safety
        else        g_pivot = 1;         // includes b==-1 fallback (take all positives)
    }
}

// ---------------- main pass: zero out, collect candidates ----------------
__global__ void __launch_bounds__(256) k_main(const float4* __restrict__ x,
                                              float4* __restrict__ out, int n4) {
    __shared__ int s_cnt;
    __shared__ int s_base;
    __shared__ unsigned long long s_buf[SBUF_CAP];
    if (threadIdx.x == 0) s_cnt = 0;
    __syncthreads();

    const float pv = __int_as_float(g_pivot << 19);
    const float4 Z = make_float4(0.f, 0.f, 0.f, 0.f);
    int n16 = n4 >> 2;                       // groups of 4 float4 = 16 floats
    int stride = gridDim.x * blockDim.x;
    int i = blockIdx.x * blockDim.x + threadIdx.x;

    for (; i < n16; i += stride) {
        int j = i << 2;                       // first float4 index of this group
        float4 v0 = x[j], v1 = x[j + 1], v2 = x[j + 2], v3 = x[j + 3];
        out[j] = Z; out[j + 1] = Z; out[j + 2] = Z; out[j + 3] = Z;
        float m0 = fmaxf(fmaxf(v0.x, v0.y), fmaxf(v0.z, v0.w));
        float m1 = fmaxf(fmaxf(v1.x, v1.y), fmaxf(v1.z, v1.w));
        float m2 = fmaxf(fmaxf(v2.x, v2.y), fmaxf(v2.z, v2.w));
        float m3 = fmaxf(fmaxf(v3.x, v3.y), fmaxf(v3.z, v3.w));
        float m = fmaxf(fmaxf(m0, m1), fmaxf(m2, m3));
        if (m >= pv) {                        // rare (~20% of warps, ~3% of groups)
            const float* e = (const float*)&v0;   // v0..v3 are contiguous? not guaranteed.
            float vals[16] = {v0.x, v0.y, v0.z, v0.w, v1.x, v1.y, v1.z, v1.w,
                              v2.x, v2.y, v2.z, v2.w, v3.x, v3.y, v3.z, v3.w};
            (void)e;
            unsigned base_idx = (unsigned)j * 4u;
            #pragma unroll
            for (int c = 0; c < 16; c++) {
                if (vals[c] >= pv) {
                    unsigned bits = __float_as_uint(vals[c]);
                    unsigned long long pk =
                        ((unsigned long long)bits << 32) | (unsigned long long)(base_idx + c);
                    int sl = atomicAdd(&s_cnt, 1);
                    if (sl < SBUF_CAP) {
                        s_buf[sl] = pk;
                    } else {
                        int p = atomicAdd(&g_cand_n, 1);
                        if (p < CAND_CAP) g_cand[p] = pk;
                    }
                }
            }
        }
    }
    // tail elements (n4 % 4 float4s) handled by thread 0 of block 0
    if (blockIdx.x == 0 && threadIdx.x == 0) {
        for (int j = n16 << 2; j < n4; j++) {
            float4 v = x[j];
            out[j] = Z;
            float vv[4] = {v.x, v.y, v.z, v.w};
            for (int c = 0; c < 4; c++) {
                if (vv[c] >= pv) {
                    unsigned bits = __float_as_uint(vv[c]);
                    int p = atomicAdd(&g_cand_n, 1);
                    if (p < CAND_CAP)
                        g_cand[p] = ((unsigned long long)bits << 32) |
                                    (unsigned long long)((unsigned)j * 4u + c);
                }
            }
        }
    }
    __syncthreads();
    int cnt = s_cnt; if (cnt > SBUF_CAP) cnt = SBUF_CAP;
    if (threadIdx.x == 0) s_base = atomicAdd(&g_cand_n, cnt);
    __syncthreads();
    for (int t = threadIdx.x; t < cnt; t += blockDim.x) {
        int sl = s_base + t;
        if (sl < CAND_CAP) g_cand[sl] = s_buf[t];
    }
}

// ---------------- level-1 histogram of candidates (key = bits>>19) ----------------
__global__ void k_h1() {
    __shared__ int h[NBIN];
    for (int j = threadIdx.x; j < NBIN; j += blockDim.x) h[j] = 0;
    __syncthreads();
    int cn = g_cand_n; if (cn > CAND_CAP) cn = CAND_CAP;
    int i = blockIdx.x * blockDim.x + threadIdx.x;
    int stride = gridDim.x * blockDim.x;
    for (; i < cn; i += stride) {
        int key = (int)(g_cand[i] >> 51);   // bits >> 19
        atomicAdd(&h[key], 1);
    }
    __syncthreads();
    for (int j = threadIdx.x; j < NBIN; j += blockDim.x) {
        int c = h[j];
        if (c) atomicAdd(&g_hist1[j], c);
    }
}

__global__ void k_f1(const int* kptr, int num_samples) {
    int kk = (kptr != nullptr) ? kptr[0] : 64;
    long long nk = (long long)kk * num_samples;
    int cn = g_cand_n; if (cn > CAND_CAP) cn = CAND_CAP;
    if (nk > cn) nk = cn;
    if (nk <= 0) return;                      // defaults from k_init apply
    int b, after;
    suffix_find(g_hist1, nk, b, after);
    if (threadIdx.x == 0 && b >= 0) { g_c1 = b; g_above1 = after; }
}

// ---------------- level-2 histogram within cutoff bin (key2 = (bits>>7)&0xFFF) ----
__global__ void k_h2() {
    __shared__ int h[NBIN];
    for (int j = threadIdx.x; j < NBIN; j += blockDim.x) h[j] = 0;
    __syncthreads();
    int c1 = g_c1;
    int cn = g_cand_n; if (cn > CAND_CAP) cn = CAND_CAP;
    int i = blockIdx.x * blockDim.x + threadIdx.x;
    int stride = gridDim.x * blockDim.x;
    for (; i < cn; i += stride) {
        unsigned long long p = g_cand[i];
        if ((int)(p >> 51) == c1) {
            int k2 = (int)(p >> 39) & 0xFFF;
            atomicAdd(&h[k2], 1);
        }
    }
    __syncthreads();
    for (int j = threadIdx.x; j < NBIN; j += blockDim.x) {
        int c = h[j];
        if (c) atomicAdd(&g_hist2[j], c);
    }
}

__global__ void k_f2(const int* kptr, int num_samples) {
    int kk = (kptr != nullptr) ? kptr[0] : 64;
    long long nk = (long long)kk * num_samples;
    int cn = g_cand_n; if (cn > CAND_CAP) cn = CAND_CAP;
    if (nk > cn) nk = cn;
    long long t2 = nk - g_above1;
    if (t2 <= 0) return;
    int b, after;
    suffix_find(g_hist2, t2, b, after);
    if (threadIdx.x == 0 && b >= 0) { g_b2 = b; g_need = (int)(t2 - after); }
}

// ---------------- write winners / collect exact-bin ties ----------------
__global__ void k_write(float* __restrict__ out) {
    int c1 = g_c1, b2 = g_b2;
    int cn = g_cand_n; if (cn > CAND_CAP) cn = CAND_CAP;
    int i = blockIdx.x * blockDim.x + threadIdx.x;
    int stride = gridDim.x * blockDim.x;
    for (; i < cn; i += stride) {
        unsigned long long p = g_cand[i];
        int key = (int)(p >> 51);
        if (key > c1) {
            out[(unsigned)p] = __uint_as_float((unsigned)(p >> 32));
        } else if (key == c1) {
            int k2 = (int)(p >> 39) & 0xFFF;
            if (k2 > b2) {
                out[(unsigned)p] = __uint_as_float((unsigned)(p >> 32));
            } else if (k2 == b2) {
                int s = atomicAdd(&g_cand2_n, 1);
                if (s < CAP2) g_cand2[s] = p;
            }
        }
    }
}

// ---------------- exact tie-break in the final 24-bit bin ----------------
__global__ void k_res(float* __restrict__ out) {
    int n = g_cand2_n; if (n > CAP2) n = CAP2;
    int need = g_need;
    int i = blockIdx.x * blockDim.x + threadIdx.x;
    int stride = gridDim.x * blockDim.x;
    for (; i < n; i += stride) {
        unsigned long long ci = g_cand2[i];
        unsigned bi = (unsigned)(ci >> 32), ii = (unsigned)ci;
        int rank = 0;
        for (int jj = 0; jj < n; jj++) {
            unsigned long long cj = g_cand2[jj];
            unsigned bj = (unsigned)(cj >> 32), ij = (unsigned)cj;
            rank += (bj > bi) || (bj == bi && ij < ii);
        }
        if (rank < need) out[ii] = __uint_as_float(bi);
    }
}

// ---------------- launch ----------------
extern "C" void kernel_launch(void* const* d_in, const int* in_sizes, int n_in,
                              void* d_out, int out_size) {
    const float* x  = (const float*)d_in[0];
    const int* kptr = (n_in >= 2) ? (const int*)d_in[1] : nullptr;
    float* out      = (float*)d_out;

    int n  = in_sizes[0];
    int n4 = n / 4;
    int nsamp4 = n4 / 64;
    int num_samples = n / LAST_DIM;

    k_init  <<<16, 256>>>();
    k_sample<<<148, 256>>>((const float4*)x, nsamp4);
    k_pivot <<<1, 1024>>>(kptr, num_samples);
    k_main  <<<2048, 256>>>((const float4*)x, (float4*)out, n4);
    k_h1    <<<148, 256>>>();
    k_f1    <<<1, 1024>>>(kptr, num_samples);
    k_h2    <<<148, 256>>>();
    k_f2    <<<1, 1024>>>(kptr, num_samples);
    k_write <<<512, 256>>>(out);
    k_res   <<<32, 256>>>(out);
}

// round 4
// speedup vs baseline: 6.3165x; 1.1827x over previous
#include <cuda_runtime.h>
#include <stdint.h>

#define NBIN      4096
#define CAND_CAP  (16*1024*1024)
#define CAP2      16384
#define SBUF_CAP  1024
#define LAST_DIM  16384

// ---------------- persistent device state (cleared every launch) ----------------
__device__ int                g_shist[NBIN];   // sampled histogram (12-bit key)
__device__ int                g_hist1[NBIN];   // candidate histogram level 1
__device__ int                g_hist2[NBIN];   // candidate histogram level 2
__device__ unsigned long long g_cand[CAND_CAP];
__device__ unsigned long long g_cand2[CAP2];
__device__ int g_cand_n, g_cand2_n;
__device__ int g_pivot;                         // coarse bin pivot (12-bit key space)
__device__ int g_c1, g_above1;
__device__ int g_b2, g_need;

// ---------------- init ----------------
__global__ void k_init() {
    int i = blockIdx.x * blockDim.x + threadIdx.x;
    if (i < NBIN) { g_shist[i] = 0; g_hist1[i] = 0; g_hist2[i] = 0; }
    if (i == 0) {
        g_cand_n = 0; g_cand2_n = 0;
        g_pivot = 1;                  // fallback: all positives are candidates
        g_c1 = 0x7fffffff; g_above1 = 0;
        g_b2 = 0x7fffffff; g_need = 0;
    }
}

// ---------------- sampled histogram (1/64 of elements, warp-coalesced) ----------
// warp w reads float4s [c*2048, c*2048+32) for chunks c = w, w+nw, ...
__global__ void k_sample(const float4* __restrict__ x, int nchunk) {
    __shared__ int h[NBIN];
    for (int j = threadIdx.x; j < NBIN; j += blockDim.x) h[j] = 0;
    __syncthreads();
    int gw   = (blockIdx.x * blockDim.x + threadIdx.x) >> 5;
    int lane = threadIdx.x & 31;
    int nw   = (gridDim.x * blockDim.x) >> 5;
    for (int c = gw; c < nchunk; c += nw) {
        float4 v = x[(size_t)c * 2048 + lane];
        int b0 = __float_as_int(v.x), b1 = __float_as_int(v.y);
        int b2 = __float_as_int(v.z), b3 = __float_as_int(v.w);
        if (b0 > 0) atomicAdd(&h[b0 >> 19], 1);
        if (b1 > 0) atomicAdd(&h[b1 >> 19], 1);
        if (b2 > 0) atomicAdd(&h[b2 >> 19], 1);
        if (b3 > 0) atomicAdd(&h[b3 >> 19], 1);
    }
    __syncthreads();
    for (int j = threadIdx.x; j < NBIN; j += blockDim.x) {
        int c = h[j];
        if (c) atomicAdd(&g_shist[j], c);
    }
}

// ---------------- suffix-boundary finder (one block, 1024 threads) ----------------
__device__ void suffix_find(const int* hist, long long target, int& b_out, int& after_out) {
    __shared__ int ssum[1024];
    __shared__ int sh_b, sh_after;
    int t = threadIdx.x;
    if (t == 0) { sh_b = -1; sh_after = 0; }
    int b0 = 4 * t;
    int h0 = hist[b0], h1 = hist[b0 + 1], h2 = hist[b0 + 2], h3 = hist[b0 + 3];
    int l3 = h3, l2 = h2 + l3, l1 = h1 + l2, l0 = h0 + l1;
    ssum[t] = l0;
    __syncthreads();
    for (int off = 1; off < 1024; off <<= 1) {
        int v = (t + off < 1024) ? ssum[t + off] : 0;
        __syncthreads();
        ssum[t] += v;
        __syncthreads();
    }
    int after = (t + 1 < 1024) ? ssum[t + 1] : 0;
    long long s0 = (long long)l0 + after, s1 = (long long)l1 + after;
    long long s2 = (long long)l2 + after, s3 = (long long)l3 + after, s4 = after;
    if (s0 >= target && s1 < target) { sh_b = b0;     sh_after = (int)s1; }
    if (s1 >= target && s2 < target) { sh_b = b0 + 1; sh_after = (int)s2; }
    if (s2 >= target && s3 < target) { sh_b = b0 + 2; sh_after = (int)s3; }
    if (s3 >= target && s4 < target) { sh_b = b0 + 3; sh_after = (int)s4; }
    __syncthreads();
    b_out = sh_b; after_out = sh_after;
}

// ---------------- pick pivot from sampled histogram ----------------
__global__ void k_pivot(const int* kptr, int num_samples) {
    int kk = (kptr != nullptr) ? kptr[0] : 64;
    long long nk = (long long)kk * num_samples;
    long long target = (nk * 135) / (100 * 64) + 256;   // 1.35x expected + slack (~26 sigma)
    if (target < 1) target = 1;
    int b, after;
    suffix_find(g_shist, target, b, after);
    if (threadIdx.x == 0) g_pivot = (b >= 1) ? b : 1;
}

// ---------------- candidate push helper ----------------
__device__ __forceinline__ void push_cand(unsigned bits, unsigned idx,
                                          int* s_cnt, unsigned long long* s_buf) {
    unsigned long long pk = ((unsigned long long)bits << 32) | (unsigned long long)idx;
    int sl = atomicAdd(s_cnt, 1);
    if (sl < SBUF_CAP) {
        s_buf[sl] = pk;
    } else {
        int p = atomicAdd(&g_cand_n, 1);
        if (p < CAND_CAP) g_cand[p] = pk;
    }
}

// ---------------- main pass: zero out, collect candidates (fully coalesced) -------
__global__ void __launch_bounds__(256) k_main(const float4* __restrict__ x,
                                              float4* __restrict__ out, int n4) {
    __shared__ int s_cnt;
    __shared__ int s_base;
    __shared__ unsigned long long s_buf[SBUF_CAP];
    if (threadIdx.x == 0) s_cnt = 0;
    __syncthreads();

    const float pv = __int_as_float(g_pivot << 19);
    const float4 Z = make_float4(0.f, 0.f, 0.f, 0.f);
    int t = threadIdx.x;
    int ntile = n4 >> 10;                     // tiles of 1024 float4s

    for (int tile = blockIdx.x; tile < ntile; tile += gridDim.x) {
        int base = tile << 10;
        float4 v0 = x[base + t];
        float4 v1 = x[base + 256 + t];
        float4 v2 = x[base + 512 + t];
        float4 v3 = x[base + 768 + t];
        out[base + t]       = Z;
        out[base + 256 + t] = Z;
        out[base + 512 + t] = Z;
        out[base + 768 + t] = Z;
        float m0 = fmaxf(fmaxf(v0.x, v0.y), fmaxf(v0.z, v0.w));
        float m1 = fmaxf(fmaxf(v1.x, v1.y), fmaxf(v1.z, v1.w));
        float m2 = fmaxf(fmaxf(v2.x, v2.y), fmaxf(v2.z, v2.w));
        float m3 = fmaxf(fmaxf(v3.x, v3.y), fmaxf(v3.z, v3.w));
        if (fmaxf(fmaxf(m0, m1), fmaxf(m2, m3)) >= pv) {   // rare path
            float4 vv[4] = {v0, v1, v2, v3};
            #pragma unroll
            for (int q = 0; q < 4; q++) {
                unsigned fidx = (unsigned)(base + q * 256 + t) * 4u;
                float e[4] = {vv[q].x, vv[q].y, vv[q].z, vv[q].w};
                #pragma unroll
                for (int c = 0; c < 4; c++) {
                    if (e[c] >= pv)
                        push_cand(__float_as_uint(e[c]), fidx + c, &s_cnt, s_buf);
                }
            }
        }
    }
    // tail float4s (none for the reference shape; generic safety)
    for (int j = (ntile << 10) + blockIdx.x * blockDim.x + t; j < n4;
         j += gridDim.x * blockDim.x) {
        float4 v = x[j];
        out[j] = Z;
        float e[4] = {v.x, v.y, v.z, v.w};
        #pragma unroll
        for (int c = 0; c < 4; c++) {
            if (e[c] >= pv)
                push_cand(__float_as_uint(e[c]), (unsigned)j * 4u + c, &s_cnt, s_buf);
        }
    }
    __syncthreads();
    int cnt = s_cnt; if (cnt > SBUF_CAP) cnt = SBUF_CAP;
    if (threadIdx.x == 0) s_base = atomicAdd(&g_cand_n, cnt);
    __syncthreads();
    for (int q = threadIdx.x; q < cnt; q += blockDim.x) {
        int sl = s_base + q;
        if (sl < CAND_CAP) g_cand[sl] = s_buf[q];
    }
}

// ---------------- level-1 histogram of candidates (key = bits>>19) ----------------
__global__ void k_h1() {
    __shared__ int h[NBIN];
    for (int j = threadIdx.x; j < NBIN; j += blockDim.x) h[j] = 0;
    __syncthreads();
    int cn = g_cand_n; if (cn > CAND_CAP) cn = CAND_CAP;
    int i = blockIdx.x * blockDim.x + threadIdx.x;
    int stride = gridDim.x * blockDim.x;
    for (; i < cn; i += stride) {
        int key = (int)(g_cand[i] >> 51);   // bits >> 19
        atomicAdd(&h[key], 1);
    }
    __syncthreads();
    for (int j = threadIdx.x; j < NBIN; j += blockDim.x) {
        int c = h[j];
        if (c) atomicAdd(&g_hist1[j], c);
    }
}

__global__ void k_f1(const int* kptr, int num_samples) {
    int kk = (kptr != nullptr) ? kptr[0] : 64;
    long long nk = (long long)kk * num_samples;
    int cn = g_cand_n; if (cn > CAND_CAP) cn = CAND_CAP;
    if (nk > cn) nk = cn;
    if (nk <= 0) return;
    int b, after;
    suffix_find(g_hist1, nk, b, after);
    if (threadIdx.x == 0 && b >= 0) { g_c1 = b; g_above1 = after; }
}

// ---------------- level-2 histogram within cutoff bin (key2 = (bits>>7)&0xFFF) ----
__global__ void k_h2() {
    __shared__ int h[NBIN];
    for (int j = threadIdx.x; j < NBIN; j += blockDim.x) h[j] = 0;
    __syncthreads();
    int c1 = g_c1;
    int cn = g_cand_n; if (cn > CAND_CAP) cn = CAND_CAP;
    int i = blockIdx.x * blockDim.x + threadIdx.x;
    int stride = gridDim.x * blockDim.x;
    for (; i < cn; i += stride) {
        unsigned long long p = g_cand[i];
        if ((int)(p >> 51) == c1) {
            int k2 = (int)(p >> 39) & 0xFFF;
            atomicAdd(&h[k2], 1);
        }
    }
    __syncthreads();
    for (int j = threadIdx.x; j < NBIN; j += blockDim.x) {
        int c = h[j];
        if (c) atomicAdd(&g_hist2[j], c);
    }
}

__global__ void k_f2(const int* kptr, int num_samples) {
    int kk = (kptr != nullptr) ? kptr[0] : 64;
    long long nk = (long long)kk * num_samples;
    int cn = g_cand_n; if (cn > CAND_CAP) cn = CAND_CAP;
    if (nk > cn) nk = cn;
    long long t2 = nk - g_above1;
    if (t2 <= 0) return;
    int b, after;
    suffix_find(g_hist2, t2, b, after);
    if (threadIdx.x == 0 && b >= 0) { g_b2 = b; g_need = (int)(t2 - after); }
}

// ---------------- write winners / collect exact-bin ties ----------------
__global__ void k_write(float* __restrict__ out) {
    int c1 = g_c1, b2 = g_b2;
    int cn = g_cand_n; if (cn > CAND_CAP) cn = CAND_CAP;
    int i = blockIdx.x * blockDim.x + threadIdx.x;
    int stride = gridDim.x * blockDim.x;
    for (; i < cn; i += stride) {
        unsigned long long p = g_cand[i];
        int key = (int)(p >> 51);
        if (key > c1) {
            out[(unsigned)p] = __uint_as_float((unsigned)(p >> 32));
        } else if (key == c1) {
            int k2 = (int)(p >> 39) & 0xFFF;
            if (k2 > b2) {
                out[(unsigned)p] = __uint_as_float((unsigned)(p >> 32));
            } else if (k2 == b2) {
                int s = atomicAdd(&g_cand2_n, 1);
                if (s < CAP2) g_cand2[s] = p;
            }
        }
    }
}

// ---------------- exact tie-break in the final 24-bit bin ----------------
__global__ void k_res(float* __restrict__ out) {
    int n = g_cand2_n; if (n > CAP2) n = CAP2;
    int need = g_need;
    int i = blockIdx.x * blockDim.x + threadIdx.x;
    int stride = gridDim.x * blockDim.x;
    for (; i < n; i += stride) {
        unsigned long long ci = g_cand2[i];
        unsigned bi = (unsigned)(ci >> 32), ii = (unsigned)ci;
        int rank = 0;
        for (int jj = 0; jj < n; jj++) {
            unsigned long long cj = g_cand2[jj];
            unsigned bj = (unsigned)(cj >> 32), ij = (unsigned)cj;
            rank += (bj > bi) || (bj == bi && ij < ii);
        }
        if (rank < need) out[ii] = __uint_as_float(bi);
    }
}

// ---------------- launch ----------------
extern "C" void kernel_launch(void* const* d_in, const int* in_sizes, int n_in,
                              void* d_out, int out_size) {
    const float* x  = (const float*)d_in[0];
    const int* kptr = (n_in >= 2) ? (const int*)d_in[1] : nullptr;
    float* out      = (float*)d_out;

    int n  = in_sizes[0];
    int n4 = n / 4;
    int nchunk = n4 / 2048;
    int num_samples = n / LAST_DIM;

    k_init  <<<16, 256>>>();
    k_sample<<<148, 256>>>((const float4*)x, nchunk);
    k_pivot <<<1, 1024>>>(kptr, num_samples);
    k_main  <<<2048, 256>>>((const float4*)x, (float4*)out, n4);
    k_h1    <<<148, 256>>>();
    k_f1    <<<1, 1024>>>(kptr, num_samples);
    k_h2    <<<148, 256>>>();
    k_f2    <<<1, 1024>>>(kptr, num_samples);
    k_write <<<512, 256>>>(out);
    k_res   <<<32, 256>>>(out);
}